// round 8
// baseline (speedup 1.0000x reference)
#include <cuda_runtime.h>
#include <cuda_fp16.h>
#include <math.h>

#define B 128
#define C 6
#define H 224
#define W 224
#define HWSZ (H*W)          // 50176
#define HW4 (HWSZ/4)        // 12544
#define HW2 (HWSZ/2)        // 25088 half2 per channel
#define POOL 7
#define NS (POOL*POOL)      // 49
#define BC (B*C)            // 768
#define CS (C*NS)           // 294
#define FEAT (3*C)          // 18
#define W4 (W/4)            // 56 float4 per row
#define WH2 (W/2)           // 112 half2 per row
#define GRID1 148           // persistent blocks (1/SM)
#define NFULL (BC - (BC/GRID1)*GRID1)   // 28 blocks get an extra channel

__device__ float g_pooled[BC * NS];

__constant__ float c_prior[36] = {
    1.0f,  0.0f,  0.6f,  0.0f, -2.0f, 0.0f,
    0.0f,  1.0f,  0.6f,  0.0f,  0.0f, 0.0f,
    0.1f,  0.1f,  0.5f,  0.0f,  0.0f, 0.0f,
    0.0f,  0.0f,  0.0f,  1.0f,  0.0f, 0.0f,
    0.0f,  0.0f,  0.0f,  0.0f,  1.0f, 0.2f,
    0.0f, -0.6f, -0.6f, -0.6f,  0.6f, 1.0f
};
__constant__ float c_sign[6] = {1.f, -1.f, 1.f, -1.f, 1.f, 1.f};

__device__ __forceinline__ float tanh_f(float x) {
    float y;
    asm("tanh.approx.f32 %0, %1;" : "=f"(y) : "f"(x));
    return y;
}
__device__ __forceinline__ unsigned h2u(__half2 h) { return *(unsigned*)&h; }

// ---------------------------------------------------------------------------
// Kernel 1: persistent warp-specialized producer/consumer.
//   producers (warps 0-7): stream channel i from DRAM (fp32), fp32 stats,
//     fp16 pack -> buf[i&1]. Batched 7-deep loads for MLP.
//   consumers (warps 8-15): gate (fp32 tanh) + 32x32 pool of channel i-1
//     from buf[(i-1)&1] using the stats partials written last stage.
// DRAM streaming never stalls on gate compute.
// sigmoid((x-m)/s/0.5) pooled = 0.5 + mean(tanh((x-m)/s))/2
// ---------------------------------------------------------------------------
__global__ __launch_bounds__(512, 1)
void gate_pool_kernel(const float* __restrict__ x)
{
    extern __shared__ __align__(16) __half2 sbuf[];   // 2 * 25088 half2 = 200704 B
    __shared__ float psum[2][8], psq[2][8];

    const int blk  = blockIdx.x;
    const int n_ch = (BC / GRID1) + (blk < NFULL ? 1 : 0);   // 6 or 5
    const int tid  = threadIdx.x;
    const int warp = tid >> 5, lane = tid & 31;

    for (int i = 0; i <= n_ch; ++i) {
        if (warp < 8) {
            // ---------------- producer ----------------
            if (i < n_ch) {
                const int ch = blk + i * GRID1;
                const float4* __restrict__ xin =
                    (const float4*)(x + (size_t)ch * HWSZ) + tid;
                uint2* __restrict__ s64 = (uint2*)(sbuf + (i & 1) * HW2) + tid;
                float sum = 0.f, sq = 0.f;
                #pragma unroll
                for (int g = 0; g < 7; ++g) {           // 49 = 7 groups of 7
                    float4 v[7];
                    #pragma unroll
                    for (int k = 0; k < 7; ++k)
                        v[k] = __ldcs(xin + (g * 7 + k) * 256);
                    #pragma unroll
                    for (int k = 0; k < 7; ++k) {
                        sum += (v[k].x + v[k].y) + (v[k].z + v[k].w);
                        sq  += fmaf(v[k].x, v[k].x, fmaf(v[k].y, v[k].y,
                               fmaf(v[k].z, v[k].z, v[k].w * v[k].w)));
                        uint2 u;
                        u.x = h2u(__floats2half2_rn(v[k].x, v[k].y));
                        u.y = h2u(__floats2half2_rn(v[k].z, v[k].w));
                        s64[(g * 7 + k) * 256] = u;
                    }
                }
                #pragma unroll
                for (int o = 16; o; o >>= 1) {
                    sum += __shfl_down_sync(0xffffffffu, sum, o);
                    sq  += __shfl_down_sync(0xffffffffu, sq,  o);
                }
                if (lane == 0) { psum[i & 1][warp] = sum; psq[i & 1][warp] = sq; }
            }
        } else {
            // ---------------- consumer ----------------
            if (i > 0) {
                const int p  = (i - 1) & 1;
                const int ch = blk + (i - 1) * GRID1;
                float sum = 0.f, sq = 0.f;
                #pragma unroll
                for (int k = 0; k < 8; ++k) { sum += psum[p][k]; sq += psq[p][k]; }
                const float invN = 1.0f / (float)HWSZ;
                const float mean = sum * invN;
                const float var  = fmaxf((sq - sum * sum * invN)
                                         * (1.0f / (float)(HWSZ - 1)), 0.f);
                const float s2 = 1.0f / (sqrtf(var) + 1e-5f);
                const float o2 = -mean * s2;

                const __half2* __restrict__ buf = sbuf + p * HW2;
                const int wc  = warp - 8;
                const int r2  = lane >> 4;      // row parity in window
                const int c16 = lane & 15;      // half2 col in window
                for (int win = wc; win < NS; win += 8) {
                    const int py = win / POOL, px = win - py * POOL;
                    const __half2* __restrict__ basep =
                        buf + (py * 32 + r2) * WH2 + px * 16 + c16;
                    float acc = 0.f;
                    #pragma unroll
                    for (int rp = 0; rp < 16; ++rp) {   // rows r2, r2+2, ...
                        float2 f = __half22float2(basep[rp * 2 * WH2]);
                        acc += tanh_f(fmaf(f.x, s2, o2))
                             + tanh_f(fmaf(f.y, s2, o2));
                    }
                    #pragma unroll
                    for (int o = 16; o; o >>= 1)
                        acc += __shfl_down_sync(0xffffffffu, acc, o);
                    if (lane == 0)
                        g_pooled[ch * NS + win] = acc * (1.0f / 2048.0f) + 0.5f;
                }
            }
        }
        __syncthreads();   // stage boundary: buffers/partials swap safely
    }
}

// ---------------------------------------------------------------------------
// Kernel 2 (fused): graph mixing + feature pooling + structured upsample.
// 448 threads: thread = (segment s in 0..7, float4-column c4 in 0..55).
// ---------------------------------------------------------------------------
__global__ __launch_bounds__(448)
void graph_upsample_kernel(const float* __restrict__ P_delta,
                           float* __restrict__ feat_out,
                           float* __restrict__ out)
{
    __shared__ float xs[CS], sal[CS], tmp[NS];
    __shared__ float Pcol[C], smean[C];
    __shared__ __align__(16) float g[52];
    __shared__ __align__(16) float4 hr4[POOL * W4];   // 7 x 56 float4

    const int bc = blockIdx.x;
    const int b = bc / C, d = bc - b * C;
    const int t = threadIdx.x;

    for (int i = t; i < CS; i += 448) xs[i] = g_pooled[b * CS + i];
    if (t < C) Pcol[t] = c_prior[t * 6 + d] + 0.2f * tanhf(P_delta[t * 6 + d]);
    __syncthreads();

    if (t < C) {
        float m = 0.f;
        #pragma unroll
        for (int s = 0; s < NS; ++s) m += xs[t * NS + s];
        smean[t] = m * (1.0f / (float)NS);
    }
    __syncthreads();

    if (t < CS) {
        const int cc = t / NS;
        sal[t] = fmaxf(c_sign[cc] * (xs[t] - smean[cc]), 0.0f);
    }
    __syncthreads();

    if (t < NS) {
        tmp[t] = sal[t]        * Pcol[0] + sal[NS + t]   * Pcol[1]
               + sal[2*NS + t] * Pcol[2] + sal[3*NS + t] * Pcol[3]
               + sal[4*NS + t] * Pcol[4] + sal[5*NS + t] * Pcol[5];
    }
    __syncthreads();

    if (t < NS) {
        const int ty = t / POOL, tx = t - ty * POOL;
        float acc = 0.f;
        int s = 0;
        #pragma unroll
        for (int sy = 0; sy < POOL; ++sy) {
            const float dy2 = (float)((sy - ty) * (sy - ty));
            #pragma unroll
            for (int sx = 0; sx < POOL; ++sx, ++s) {
                const float dx = (float)(sx - tx);
                acc += __expf(-(dy2 + dx * dx) * 0.78125f) * tmp[s];
            }
        }
        g[t] = c_sign[d] * fmaxf(acc, 0.0f);
    }
    __syncthreads();

    if (t < 32) {
        float a  = g[t];
        bool hi  = (t + 32) < NS;
        float b2 = hi ? g[t + 32] : 0.f;
        float s  = a + b2;
        float mx = hi ? fmaxf(a, b2) : a;
        float mn = hi ? fminf(a, b2) : a;
        #pragma unroll
        for (int o = 16; o; o >>= 1) {
            s  += __shfl_down_sync(0xffffffffu, s,  o);
            mx  = fmaxf(mx, __shfl_down_sync(0xffffffffu, mx, o));
            mn  = fminf(mn, __shfl_down_sync(0xffffffffu, mn, o));
        }
        if (t == 0) {
            feat_out[b * FEAT + d]         = s * (1.0f / (float)NS);
            feat_out[b * FEAT + C + d]     = mx;
            feat_out[b * FEAT + 2 * C + d] = mn;
        }
    }

    {
        float* hrows = (float*)hr4;
        for (int i = t; i < POOL * W; i += 448) {
            const int r = i / W, j = i - r * W;
            const float sx = (j + 0.5f) * (1.0f / 32.0f) - 0.5f;
            const float x0f = floorf(sx);
            const float fx = sx - x0f;
            const int x0 = max(0, min(6, (int)x0f));
            const int x1 = max(0, min(6, (int)x0f + 1));
            const float a = g[r * POOL + x0];
            hrows[r * W + j] = a + fx * (g[r * POOL + x1] - a);
        }
    }
    __syncthreads();

    {
        const int s  = t / W4;           // 0..7
        const int c4 = t - s * W4;       // 0..55
        const bool edge = (s == 0) | (s == 7);
        const int y0 = (s == 0) ? 0 : (s - 1);
        const int y1 = (s == 7) ? 6 : s;
        const int row0 = (s == 0) ? 0 : (32 * s - 16);
        const int n = edge ? 16 : 32;

        const float4 a = hr4[y0 * W4 + c4];
        const float4 bb = hr4[y1 * W4 + c4];
        const float dxv = bb.x - a.x, dyv = bb.y - a.y;
        const float dzv = bb.z - a.z, dwv = bb.w - a.w;

        float4* __restrict__ o = (float4*)(out + (size_t)bc * HWSZ) + row0 * W4 + c4;
        #pragma unroll
        for (int r = 0; r < 32; ++r) {
            if (r < n) {
                const float fy = 0.015625f + (float)r * 0.03125f;
                float4 v;
                v.x = fmaf(fy, dxv, a.x);
                v.y = fmaf(fy, dyv, a.y);
                v.z = fmaf(fy, dzv, a.z);
                v.w = fmaf(fy, dwv, a.w);
                __stcs(&o[r * W4], v);
            }
        }
    }
}

// ---------------------------------------------------------------------------
extern "C" void kernel_launch(void* const* d_in, const int* in_sizes, int n_in,
                              void* d_out, int out_size)
{
    const float* x       = (const float*)d_in[0];   // (128,6,224,224) f32
    const float* P_delta = (const float*)d_in[1];   // (6,6) f32
    float* out = (float*)d_out;                     // [B*18 | B*C*H*W]

    const int SMEM1 = 2 * HW2 * 4;   // 200704 B double fp16 buffer
    cudaFuncSetAttribute(gate_pool_kernel,
                         cudaFuncAttributeMaxDynamicSharedMemorySize, SMEM1);

    gate_pool_kernel<<<GRID1, 512, SMEM1>>>(x);
    graph_upsample_kernel<<<BC, 448>>>(P_delta, out, out + (size_t)B * FEAT);
}

// round 10
// speedup vs baseline: 1.0502x; 1.0502x over previous
#include <cuda_runtime.h>
#include <math.h>

#define B 128
#define C 6
#define H 224
#define W 224
#define HWSZ (H*W)          // 50176
#define HW4 (HWSZ/4)        // 12544 float4 per channel
#define POOL 7
#define NS (POOL*POOL)      // 49
#define BC (B*C)            // 768
#define CS (C*NS)           // 294
#define FEAT (3*C)          // 18
#define W4 (W/4)            // 56 float4 per row
#define NT1 512

__device__ float g_pooled[BC * NS];

__constant__ float c_prior[36] = {
    1.0f,  0.0f,  0.6f,  0.0f, -2.0f, 0.0f,
    0.0f,  1.0f,  0.6f,  0.0f,  0.0f, 0.0f,
    0.1f,  0.1f,  0.5f,  0.0f,  0.0f, 0.0f,
    0.0f,  0.0f,  0.0f,  1.0f,  0.0f, 0.0f,
    0.0f,  0.0f,  0.0f,  0.0f,  1.0f, 0.2f,
    0.0f, -0.6f, -0.6f, -0.6f,  0.6f, 1.0f
};
__constant__ float c_sign[6] = {1.f, -1.f, 1.f, -1.f, 1.f, 1.f};

__device__ __forceinline__ float tanh_f(float x) {
    float y;
    asm("tanh.approx.f32 %0, %1;" : "=f"(y) : "f"(x));
    return y;
}

// gate + pool one 32x32 window of channel xc (reads hit L2).
__device__ __forceinline__ void do_window(
    const float* __restrict__ xc, float sc, float of,
    int win, int lane, float* __restrict__ out)
{
    const int sub = lane >> 3, c4 = lane & 7;
    const int py = win / POOL, px = win - py * POOL;
    const float4* __restrict__ base =
        (const float4*)(xc + (py * 32 + sub) * W + px * 32) + c4;
    float acc = 0.f;
    #pragma unroll
    for (int r = 0; r < 8; ++r) {               // rows sub, sub+4, ..., sub+28
        float4 u = base[r * W];
        acc += tanh_f(fmaf(u.x, sc, of));
        acc += tanh_f(fmaf(u.y, sc, of));
        acc += tanh_f(fmaf(u.z, sc, of));
        acc += tanh_f(fmaf(u.w, sc, of));
    }
    #pragma unroll
    for (int o = 16; o; o >>= 1) acc += __shfl_down_sync(0xffffffffu, acc, o);
    if (lane == 0) *out = acc * (1.0f / 2048.0f) + 0.5f;
}

// ---------------------------------------------------------------------------
// Kernel 1: one block per BATCH (128 blocks = single wave), 512 threads.
// Software pipeline per channel stage c (window passes cover ALL 49 windows:
// warp, 16+warp, 32+warp, and warp 0 takes window 48):
//   [wins 0-15 of ch c]   [consume reg-batch A of ch c+1, issue batch B]
//   [wins 16-31 of ch c]  [consume B, block-reduce stats]
//   [wins 32-48 of ch c]  [finalize stats c+1, issue batch A of ch c+2]
// 12-deep float4 register batches from 16 warps ~= 100KB reads in flight/SM.
// Window reads of ch c hit L2 (concurrent footprint << L2).
// sigmoid pooled = 0.5 + mean(tanh((x-m)/std))/2
// ---------------------------------------------------------------------------
__global__ __launch_bounds__(NT1, 1)
void gate_pool_kernel(const float* __restrict__ x)
{
    __shared__ float ra[16], rb[16];
    __shared__ float s_sc, s_of;

    const int b = blockIdx.x;
    const float* __restrict__ xb = x + (size_t)b * (C * HWSZ);
    const int tid = threadIdx.x;
    const int warp = tid >> 5, lane = tid & 31;
    const bool tl = tid < 256;

    float4 v[12], vt;
    float psum, psq;

    // per channel: A = [0,6144) + tail [12288,12544), B = [6144,12288)
    #define LOAD_A(pp) do { \
        _Pragma("unroll") for (int k = 0; k < 12; ++k) v[k] = (pp)[k * NT1 + tid]; \
        if (tl) vt = (pp)[12288 + tid]; } while (0)
    #define LOAD_B(pp) do { \
        _Pragma("unroll") for (int k = 0; k < 12; ++k) v[k] = (pp)[6144 + k * NT1 + tid]; } while (0)
    #define ACC_V() do { \
        _Pragma("unroll") for (int k = 0; k < 12; ++k) { \
            psum += (v[k].x + v[k].y) + (v[k].z + v[k].w); \
            psq  += fmaf(v[k].x, v[k].x, fmaf(v[k].y, v[k].y, \
                    fmaf(v[k].z, v[k].z, v[k].w * v[k].w))); } } while (0)
    #define ACC_T() do { if (tl) { \
            psum += (vt.x + vt.y) + (vt.z + vt.w); \
            psq  += fmaf(vt.x, vt.x, fmaf(vt.y, vt.y, \
                    fmaf(vt.z, vt.z, vt.w * vt.w))); } } while (0)
    #define REDUCE_STATS() do { \
        _Pragma("unroll") for (int o = 16; o; o >>= 1) { \
            psum += __shfl_down_sync(0xffffffffu, psum, o); \
            psq  += __shfl_down_sync(0xffffffffu, psq,  o); } \
        if (lane == 0) { ra[warp] = psum; rb[warp] = psq; } } while (0)
    #define FINAL_STATS() do { \
        if (warp == 0) { \
            float s = (lane < 16) ? ra[lane] : 0.f; \
            float q = (lane < 16) ? rb[lane] : 0.f; \
            _Pragma("unroll") for (int o = 8; o; o >>= 1) { \
                s += __shfl_down_sync(0xffffffffu, s, o); \
                q += __shfl_down_sync(0xffffffffu, q, o); } \
            if (lane == 0) { \
                const float invN = 1.0f / (float)HWSZ; \
                float mean = s * invN; \
                float var = fmaxf((q - s * s * invN) * (1.0f / (float)(HWSZ - 1)), 0.f); \
                float is = 1.0f / (sqrtf(var) + 1e-5f); \
                s_sc = is; s_of = -mean * is; } } } while (0)

    // ---- prologue: channel 0 stats (exposed), prefetch A(1) ----
    {
        const float4* p0 = (const float4*)xb;
        LOAD_A(p0);
        psum = 0.f; psq = 0.f;
        ACC_V(); ACC_T();
        LOAD_B(p0);
        ACC_V();
        REDUCE_STATS();
        __syncthreads();
        FINAL_STATS();
        const float4* p1 = (const float4*)(xb + HWSZ);
        LOAD_A(p1);      // A(1) in flight across stage 0
        __syncthreads();
    }

    // ---- main pipeline ----
    for (int c = 0; c < C; ++c) {
        const float sc = s_sc, of = s_of;
        const float* xc = xb + (size_t)c * HWSZ;
        float* pooled = &g_pooled[(b * C + c) * NS];

        do_window(xc, sc, of, warp, lane, pooled + warp);          // 0..15

        psum = 0.f; psq = 0.f;
        if (c < C - 1) {
            ACC_V(); ACC_T();                      // consume A(c+1)
            const float4* pn = (const float4*)(xb + (size_t)(c + 1) * HWSZ);
            LOAD_B(pn);                            // B(c+1) in flight
        }

        do_window(xc, sc, of, 16 + warp, lane, pooled + 16 + warp); // 16..31

        if (c < C - 1) {
            ACC_V();                               // consume B(c+1)
            REDUCE_STATS();
        }

        do_window(xc, sc, of, 32 + warp, lane, pooled + 32 + warp); // 32..47
        if (warp == 0)
            do_window(xc, sc, of, 48, lane, pooled + 48);           // 48

        __syncthreads();
        if (c < C - 1) {
            FINAL_STATS();
            if (c < C - 2) {
                const float4* p2 = (const float4*)(xb + (size_t)(c + 2) * HWSZ);
                LOAD_A(p2);                        // A(c+2) in flight
            }
            __syncthreads();
        }
    }
}

// ---------------------------------------------------------------------------
// Kernel 2 (fused): graph mixing + feature pooling + structured upsample.
// ---------------------------------------------------------------------------
__global__ __launch_bounds__(448)
void graph_upsample_kernel(const float* __restrict__ P_delta,
                           float* __restrict__ feat_out,
                           float* __restrict__ out)
{
    __shared__ float xs[CS], sal[CS], tmp[NS];
    __shared__ float Pcol[C], smean[C];
    __shared__ __align__(16) float g[52];
    __shared__ __align__(16) float4 hr4[POOL * W4];   // 7 x 56 float4

    const int bc = blockIdx.x;
    const int b = bc / C, d = bc - b * C;
    const int t = threadIdx.x;

    for (int i = t; i < CS; i += 448) xs[i] = g_pooled[b * CS + i];
    if (t < C) Pcol[t] = c_prior[t * 6 + d] + 0.2f * tanhf(P_delta[t * 6 + d]);
    __syncthreads();

    if (t < C) {
        float m = 0.f;
        #pragma unroll
        for (int s = 0; s < NS; ++s) m += xs[t * NS + s];
        smean[t] = m * (1.0f / (float)NS);
    }
    __syncthreads();

    if (t < CS) {
        const int cc = t / NS;
        sal[t] = fmaxf(c_sign[cc] * (xs[t] - smean[cc]), 0.0f);
    }
    __syncthreads();

    if (t < NS) {
        tmp[t] = sal[t]        * Pcol[0] + sal[NS + t]   * Pcol[1]
               + sal[2*NS + t] * Pcol[2] + sal[3*NS + t] * Pcol[3]
               + sal[4*NS + t] * Pcol[4] + sal[5*NS + t] * Pcol[5];
    }
    __syncthreads();

    if (t < NS) {
        const int ty = t / POOL, tx = t - ty * POOL;
        float acc = 0.f;
        int s = 0;
        #pragma unroll
        for (int sy = 0; sy < POOL; ++sy) {
            const float dy2 = (float)((sy - ty) * (sy - ty));
            #pragma unroll
            for (int sx = 0; sx < POOL; ++sx, ++s) {
                const float dx = (float)(sx - tx);
                acc += __expf(-(dy2 + dx * dx) * 0.78125f) * tmp[s];
            }
        }
        g[t] = c_sign[d] * fmaxf(acc, 0.0f);
    }
    __syncthreads();

    if (t < 32) {
        float a  = g[t];
        bool hi  = (t + 32) < NS;
        float b2 = hi ? g[t + 32] : 0.f;
        float s  = a + b2;
        float mx = hi ? fmaxf(a, b2) : a;
        float mn = hi ? fminf(a, b2) : a;
        #pragma unroll
        for (int o = 16; o; o >>= 1) {
            s  += __shfl_down_sync(0xffffffffu, s,  o);
            mx  = fmaxf(mx, __shfl_down_sync(0xffffffffu, mx, o));
            mn  = fminf(mn, __shfl_down_sync(0xffffffffu, mn, o));
        }
        if (t == 0) {
            feat_out[b * FEAT + d]         = s * (1.0f / (float)NS);
            feat_out[b * FEAT + C + d]     = mx;
            feat_out[b * FEAT + 2 * C + d] = mn;
        }
    }

    {
        float* hrows = (float*)hr4;
        for (int i = t; i < POOL * W; i += 448) {
            const int r = i / W, j = i - r * W;
            const float sx = (j + 0.5f) * (1.0f / 32.0f) - 0.5f;
            const float x0f = floorf(sx);
            const float fx = sx - x0f;
            const int x0 = max(0, min(6, (int)x0f));
            const int x1 = max(0, min(6, (int)x0f + 1));
            const float a = g[r * POOL + x0];
            hrows[r * W + j] = a + fx * (g[r * POOL + x1] - a);
        }
    }
    __syncthreads();

    {
        const int s  = t / W4;           // 0..7
        const int c4 = t - s * W4;       // 0..55
        const bool edge = (s == 0) | (s == 7);
        const int y0 = (s == 0) ? 0 : (s - 1);
        const int y1 = (s == 7) ? 6 : s;
        const int row0 = (s == 0) ? 0 : (32 * s - 16);
        const int n = edge ? 16 : 32;

        const float4 a = hr4[y0 * W4 + c4];
        const float4 bb = hr4[y1 * W4 + c4];
        const float dxv = bb.x - a.x, dyv = bb.y - a.y;
        const float dzv = bb.z - a.z, dwv = bb.w - a.w;

        float4* __restrict__ o = (float4*)(out + (size_t)bc * HWSZ) + row0 * W4 + c4;
        #pragma unroll
        for (int r = 0; r < 32; ++r) {
            if (r < n) {
                const float fy = 0.015625f + (float)r * 0.03125f;
                float4 vv;
                vv.x = fmaf(fy, dxv, a.x);
                vv.y = fmaf(fy, dyv, a.y);
                vv.z = fmaf(fy, dzv, a.z);
                vv.w = fmaf(fy, dwv, a.w);
                __stcs(&o[r * W4], vv);
            }
        }
    }
}

// ---------------------------------------------------------------------------
extern "C" void kernel_launch(void* const* d_in, const int* in_sizes, int n_in,
                              void* d_out, int out_size)
{
    const float* x       = (const float*)d_in[0];   // (128,6,224,224) f32
    const float* P_delta = (const float*)d_in[1];   // (6,6) f32
    float* out = (float*)d_out;                     // [B*18 | B*C*H*W]

    gate_pool_kernel<<<B, NT1>>>(x);
    graph_upsample_kernel<<<BC, 448>>>(P_delta, out, out + (size_t)B * FEAT);
}